// round 6
// baseline (speedup 1.0000x reference)
#include <cuda_runtime.h>
#include <cuda_bf16.h>
#include <cstdint>

#define N_NODES 50000
#define E_EDGES 800000
#define CIN_ 32
#define COUT_ 64
#define KK 25
#define RDIM 832                 // 26 * 32  (25 spline kernels + 1 root slot)
#define CHUNKS 26
#define TILE 64                  // nodes per block
#define NBLK ((N_NODES + TILE - 1) / TILE)   // 782
#define AP 836                   // A smem pitch (floats), ≡4 mod 32 -> conflict-free frags
#define BP 36                    // B smem pitch (floats)
#define SM_FLOATS (TILE * AP + COUT_ * BP)   // 53504 + 2304 = 55808
#define SM_BYTES  (SM_FLOATS * 4)            // 223232 B

// ---- scratch (static device globals; no allocation) ----
__device__ int    g_deg[N_NODES];
__device__ int    g_off[N_NODES + 1];
__device__ int    g_cursor[N_NODES];
__device__ float4 g_edata[E_EDGES];          // {col, fx, fy, base} per CSR slot
__device__ float  g_wt[COUT_ * RDIM];        // Wfull^T  [64][832] f32

__device__ __forceinline__ float tf32_hi(float v) {
    return __uint_as_float(__float_as_uint(v) & 0xFFFFE000u);
}

// ---------------- CSR build ----------------
__global__ void k_zero_deg() {
    int i = blockIdx.x * blockDim.x + threadIdx.x;
    if (i < N_NODES) g_deg[i] = 0;
}

__global__ void k_hist(const int* __restrict__ ei) {
    int e = blockIdx.x * blockDim.x + threadIdx.x;
    if (e < E_EDGES) {
        int row = ei[e];
        row = min(max(row, 0), N_NODES - 1);
        atomicAdd(&g_deg[row], 1);
    }
}

__global__ __launch_bounds__(1024) void k_scan() {
    __shared__ int warp_sums[32];
    __shared__ int s_run;
    int tid = threadIdx.x, lane = tid & 31, wid = tid >> 5;
    if (tid == 0) s_run = 0;
    __syncthreads();
    for (int base = 0; base < N_NODES; base += 1024) {
        int i = base + tid;
        int v = (i < N_NODES) ? g_deg[i] : 0;
        int s = v;
        #pragma unroll
        for (int d = 1; d < 32; d <<= 1) {
            int t = __shfl_up_sync(0xffffffffu, s, d);
            if (lane >= d) s += t;
        }
        if (lane == 31) warp_sums[wid] = s;
        __syncthreads();
        if (wid == 0) {
            int ws = warp_sums[lane];
            #pragma unroll
            for (int d = 1; d < 32; d <<= 1) {
                int t = __shfl_up_sync(0xffffffffu, ws, d);
                if (lane >= d) ws += t;
            }
            warp_sums[lane] = ws;
        }
        __syncthreads();
        int woff = wid ? warp_sums[wid - 1] : 0;
        int excl = s_run + woff + (s - v);
        if (i < N_NODES) { g_off[i] = excl; g_cursor[i] = excl; }
        __syncthreads();
        if (tid == 0) s_run += warp_sums[31];
        __syncthreads();
    }
    if (tid == 0) g_off[N_NODES] = s_run;
}

__global__ void k_scatter(const int* __restrict__ ei,
                          const float* __restrict__ pseudo) {
    int e = blockIdx.x * blockDim.x + threadIdx.x;
    if (e < E_EDGES) {
        int row = ei[e];
        int col = ei[E_EDGES + e];
        row = min(max(row, 0), N_NODES - 1);
        col = min(max(col, 0), N_NODES - 1);
        float vx = pseudo[2 * e]     * 4.0f;   // (KS - DEGREE) = 4
        float vy = pseudo[2 * e + 1] * 4.0f;
        float flx = floorf(vx), fly = floorf(vy);
        float fx = vx - flx, fy = vy - fly;
        int lox = min(max((int)flx, 0), 3);
        int loy = min(max((int)fly, 0), 3);
        int base = lox + 5 * loy;
        int pos = atomicAdd(&g_cursor[row], 1);
        g_edata[pos] = make_float4(__int_as_float(col), fx, fy, __int_as_float(base));
    }
}

// Wfull^T:  wt[o][r] = r<800 ? weight[r][o] : root[r-800][o]
__global__ void k_prep_wt(const float* __restrict__ weight, const float* __restrict__ root) {
    int i = blockIdx.x * blockDim.x + threadIdx.x;   // i = o*832 + r
    if (i < COUT_ * RDIM) {
        int o = i / RDIM, r = i - o * RDIM;
        g_wt[i] = (r < 800) ? weight[r * COUT_ + o] : root[(r - 800) * COUT_ + o];
    }
}

// ---------------- fused: accumulate z in smem, then 3xTF32 mma GEMM ----------------
__device__ __forceinline__ void mma_tf32(float* c, const uint32_t* a, const uint32_t* b) {
    asm volatile(
        "mma.sync.aligned.m16n8k8.row.col.f32.tf32.tf32.f32 "
        "{%0,%1,%2,%3}, {%4,%5,%6,%7}, {%8,%9}, {%0,%1,%2,%3};"
        : "+f"(c[0]), "+f"(c[1]), "+f"(c[2]), "+f"(c[3])
        : "r"(a[0]), "r"(a[1]), "r"(a[2]), "r"(a[3]), "r"(b[0]), "r"(b[1]));
}

__global__ __launch_bounds__(512) void k_fused(const float* __restrict__ x,
                                               const float* __restrict__ bias,
                                               float* __restrict__ out) {
    extern __shared__ float sm[];
    float* Asm = sm;                  // [64][AP]
    float* Bsm = sm + TILE * AP;      // [64][BP]
    int tid = threadIdx.x, w = tid >> 5, lane = tid & 31;
    int n0 = blockIdx.x * TILE;

    // zero A tile (float4; TILE*AP divisible by 4)
    #pragma unroll 4
    for (int i = tid; i < TILE * AP / 4; i += 512)
        ((float4*)Asm)[i] = make_float4(0.f, 0.f, 0.f, 0.f);
    __syncthreads();

    // ---- phase 1: accumulate z for 4 nodes per warp ----
    #pragma unroll
    for (int i = 0; i < 4; ++i) {
        int nl = w * 4 + i;
        int n  = n0 + nl;
        if (n < N_NODES) {
            int s = g_off[n], e = g_off[n + 1];
            float* zr = &Asm[nl * AP];
            for (int j = s; j < e; ++j) {
                float4 ed = g_edata[j];              // uniform broadcast
                int   col  = __float_as_int(ed.x);
                float fx   = ed.y, fy = ed.z;
                int   base = __float_as_int(ed.w);
                float xv = x[col * CIN_ + lane];     // L2-resident gather
                float gx = 1.0f - fx, gy = 1.0f - fy;
                zr[(base    ) * 32 + lane] += gx * gy * xv;
                zr[(base + 1) * 32 + lane] += fx * gy * xv;
                zr[(base + 5) * 32 + lane] += gx * fy * xv;
                zr[(base + 6) * 32 + lane] += fx * fy * xv;
            }
            float inv = 1.0f / fmaxf((float)(e - s), 1.0f);
            #pragma unroll
            for (int k = 0; k < KK; ++k) zr[k * 32 + lane] *= inv;
            zr[KK * 32 + lane] = x[n * CIN_ + lane];     // root slot (unscaled)
        }
    }
    __syncthreads();

    // ---- phase 2: out_tile = A(64x832) @ Wfull(832x64), 3xTF32 ----
    int qr = lane >> 2, qc = lane & 3;
    int wm = w & 3, wn = w >> 2;       // warp grid 4 (M) x 4 (N)
    float acc[2][4];
    #pragma unroll
    for (int nt = 0; nt < 2; ++nt)
        #pragma unroll
        for (int i = 0; i < 4; ++i) acc[nt][i] = 0.0f;

    for (int ch = 0; ch < CHUNKS; ++ch) {
        int r0 = ch * 32;
        // stage B chunk: g_wt[o][r0..r0+31] -> Bsm[o][0..31]  (512 float4s)
        {
            int o = tid >> 3, k4 = (tid & 7) * 4;
            float4 v = *(const float4*)&g_wt[o * RDIM + r0 + k4];
            *(float4*)&Bsm[o * BP + k4] = v;
        }
        __syncthreads();

        #pragma unroll
        for (int k8 = 0; k8 < 4; ++k8) {
            int kb = k8 * 8;
            int ar = (wm * 16 + qr) * AP + r0 + kb + qc;
            float a0 = Asm[ar];
            float a1 = Asm[ar + 8 * AP];
            float a2 = Asm[ar + 4];
            float a3 = Asm[ar + 8 * AP + 4];
            uint32_t ah[4], al[4];
            float h;
            h = tf32_hi(a0); ah[0] = __float_as_uint(h); al[0] = __float_as_uint(a0 - h);
            h = tf32_hi(a1); ah[1] = __float_as_uint(h); al[1] = __float_as_uint(a1 - h);
            h = tf32_hi(a2); ah[2] = __float_as_uint(h); al[2] = __float_as_uint(a2 - h);
            h = tf32_hi(a3); ah[3] = __float_as_uint(h); al[3] = __float_as_uint(a3 - h);
            #pragma unroll
            for (int nt = 0; nt < 2; ++nt) {
                int bo = (wn * 16 + nt * 8 + qr) * BP + kb + qc;
                float b0 = Bsm[bo], b1 = Bsm[bo + 4];
                uint32_t bh[2], bl[2];
                h = tf32_hi(b0); bh[0] = __float_as_uint(h); bl[0] = __float_as_uint(b0 - h);
                h = tf32_hi(b1); bh[1] = __float_as_uint(h); bl[1] = __float_as_uint(b1 - h);
                mma_tf32(acc[nt], ah, bh);
                mma_tf32(acc[nt], ah, bl);
                mma_tf32(acc[nt], al, bh);
            }
        }
        __syncthreads();   // before next chunk overwrites Bsm
    }

    // ---- epilogue: bias + store ----
    int rowa = n0 + wm * 16 + qr;
    int rowb = rowa + 8;
    #pragma unroll
    for (int nt = 0; nt < 2; ++nt) {
        int col = wn * 16 + nt * 8 + 2 * qc;
        float b0 = bias[col], b1 = bias[col + 1];
        if (rowa < N_NODES)
            *(float2*)&out[rowa * COUT_ + col] = make_float2(acc[nt][0] + b0, acc[nt][1] + b1);
        if (rowb < N_NODES)
            *(float2*)&out[rowb * COUT_ + col] = make_float2(acc[nt][2] + b0, acc[nt][3] + b1);
    }
}

// ---------------- launch ----------------
extern "C" void kernel_launch(void* const* d_in, const int* in_sizes, int n_in,
                              void* d_out, int out_size) {
    const float* x      = (const float*)d_in[0];
    const int*   ei     = (const int*)d_in[1];      // JAX x64-disabled: int32
    const float* pseudo = (const float*)d_in[2];
    const float* weight = (const float*)d_in[3];
    const float* root   = (const float*)d_in[4];
    const float* bias   = (const float*)d_in[5];
    float*       out    = (float*)d_out;

    static bool attr_done = false;
    if (!attr_done) {
        cudaFuncSetAttribute(k_fused, cudaFuncAttributeMaxDynamicSharedMemorySize, SM_BYTES);
        attr_done = true;
    }

    k_zero_deg<<<(N_NODES + 255) / 256, 256>>>();
    k_hist    <<<(E_EDGES + 255) / 256, 256>>>(ei);
    k_scan    <<<1, 1024>>>();
    k_scatter <<<(E_EDGES + 255) / 256, 256>>>(ei, pseudo);
    k_prep_wt <<<(COUT_ * RDIM + 255) / 256, 256>>>(weight, root);
    k_fused   <<<NBLK, 512, SM_BYTES>>>(x, bias, out);
}

// round 7
// speedup vs baseline: 1.5464x; 1.5464x over previous
#include <cuda_runtime.h>
#include <cuda_bf16.h>
#include <cstdint>

#define N_NODES 50000
#define E_EDGES 800000
#define CIN_ 32
#define COUT_ 64
#define KK 25
#define RDIM 832                 // 26 * 32  (25 spline kernels + 1 root slot)
#define TILE_M 128
#define N_TILES ((N_NODES + TILE_M - 1) / TILE_M)   // 391
#define KCHUNK 64                // K elements per smem chunk
#define CHUNKS (RDIM / KCHUNK)   // 13
#define WPITCH 36                // smem row pitch in uint32 words (== 4 mod 32)
#define NB 196                   // scan blocks: ceil(50000/256)

// ---- scratch (static device globals; no allocation) ----
__device__ int      g_deg[N_NODES];
__device__ int      g_off[N_NODES + 1];
__device__ int      g_cursor[N_NODES];
__device__ int      g_bsum[NB];
__device__ int      g_boff[NB];
__device__ float4   g_edata[E_EDGES];              // {col, fx, fy, base} per CSR slot
__device__ uint32_t g_zp[(size_t)N_NODES * RDIM];  // packed (bf16 hi<<16 | bf16 lo), 166 MB
__device__ uint32_t g_wtp[COUT_ * RDIM];           // packed Wfull^T [64][832]

__device__ __forceinline__ uint32_t pack_bf16x2(float v) {
    __nv_bfloat16 h = __float2bfloat16(v);
    float hf = __bfloat162float(h);
    __nv_bfloat16 l = __float2bfloat16(v - hf);
    return ((uint32_t)__bfloat16_as_ushort(h) << 16) | (uint32_t)__bfloat16_as_ushort(l);
}

// ---------------- CSR build ----------------
__global__ void k_zero_deg() {
    int i = blockIdx.x * blockDim.x + threadIdx.x;
    if (i < N_NODES) g_deg[i] = 0;
}

__global__ void k_hist(const int* __restrict__ ei) {
    int e = blockIdx.x * blockDim.x + threadIdx.x;
    if (e < E_EDGES) {
        int row = ei[e];
        row = min(max(row, 0), N_NODES - 1);
        atomicAdd(&g_deg[row], 1);
    }
}

// block-sums of g_deg (256 per block)
__global__ __launch_bounds__(256) void k_bsum() {
    __shared__ int ws[8];
    int tid = threadIdx.x, lane = tid & 31, w = tid >> 5;
    int i = blockIdx.x * 256 + tid;
    int v = (i < N_NODES) ? g_deg[i] : 0;
    #pragma unroll
    for (int d = 16; d > 0; d >>= 1) v += __shfl_down_sync(0xffffffffu, v, d);
    if (lane == 0) ws[w] = v;
    __syncthreads();
    if (tid == 0) {
        int s = 0;
        #pragma unroll
        for (int j = 0; j < 8; ++j) s += ws[j];
        g_bsum[blockIdx.x] = s;
    }
}

// exclusive scan of NB block sums (single block)
__global__ __launch_bounds__(256) void k_bscan() {
    __shared__ int ws[8];
    int tid = threadIdx.x, lane = tid & 31, w = tid >> 5;
    int v = (tid < NB) ? g_bsum[tid] : 0;
    int s = v;
    #pragma unroll
    for (int d = 1; d < 32; d <<= 1) {
        int t = __shfl_up_sync(0xffffffffu, s, d);
        if (lane >= d) s += t;
    }
    if (lane == 31) ws[w] = s;
    __syncthreads();
    if (w == 0 && lane < 8) {
        int x = ws[lane];
        #pragma unroll
        for (int d = 1; d < 8; d <<= 1) {
            int t = __shfl_up_sync(0xffu, x, d);
            if (lane >= d) x += t;
        }
        ws[lane] = x;
    }
    __syncthreads();
    int woff = w ? ws[w - 1] : 0;
    if (tid < NB) g_boff[tid] = woff + s - v;
}

// per-element offsets: g_off / g_cursor
__global__ __launch_bounds__(256) void k_offsets() {
    __shared__ int ws[8];
    int tid = threadIdx.x, lane = tid & 31, w = tid >> 5;
    int i = blockIdx.x * 256 + tid;
    int v = (i < N_NODES) ? g_deg[i] : 0;
    int s = v;
    #pragma unroll
    for (int d = 1; d < 32; d <<= 1) {
        int t = __shfl_up_sync(0xffffffffu, s, d);
        if (lane >= d) s += t;
    }
    if (lane == 31) ws[w] = s;
    __syncthreads();
    if (w == 0 && lane < 8) {
        int x = ws[lane];
        #pragma unroll
        for (int d = 1; d < 8; d <<= 1) {
            int t = __shfl_up_sync(0xffu, x, d);
            if (lane >= d) x += t;
        }
        ws[lane] = x;
    }
    __syncthreads();
    int woff = w ? ws[w - 1] : 0;
    int excl = g_boff[blockIdx.x] + woff + s - v;
    if (i < N_NODES) {
        g_off[i] = excl;
        g_cursor[i] = excl;
        if (i == N_NODES - 1) g_off[N_NODES] = excl + v;
    }
}

__global__ void k_scatter(const int* __restrict__ ei,
                          const float* __restrict__ pseudo) {
    int e = blockIdx.x * blockDim.x + threadIdx.x;
    if (e < E_EDGES) {
        int row = ei[e];
        int col = ei[E_EDGES + e];
        row = min(max(row, 0), N_NODES - 1);
        col = min(max(col, 0), N_NODES - 1);
        float vx = pseudo[2 * e]     * 4.0f;   // (KS - DEGREE) = 4
        float vy = pseudo[2 * e + 1] * 4.0f;
        float flx = floorf(vx), fly = floorf(vy);
        float fx = vx - flx, fy = vy - fly;
        int lox = min(max((int)flx, 0), 3);
        int loy = min(max((int)fly, 0), 3);
        int base = lox + 5 * loy;
        int pos = atomicAdd(&g_cursor[row], 1);
        g_edata[pos] = make_float4(__int_as_float(col), fx, fy, __int_as_float(base));
    }
}

// Wfull^T packed:  wt[o][r] = r<800 ? weight[r][o] : root[r-800][o]
__global__ void k_prep_wt(const float* __restrict__ weight, const float* __restrict__ root) {
    int i = blockIdx.x * blockDim.x + threadIdx.x;   // i = o*832 + r
    if (i < COUT_ * RDIM) {
        int o = i / RDIM, r = i - o * RDIM;
        float w = (r < 800) ? weight[r * COUT_ + o] : root[(r - 800) * COUT_ + o];
        g_wtp[i] = pack_bf16x2(w);
    }
}

// ---------------- per-node z accumulation (warp per node, no atomics) ----------------
__global__ __launch_bounds__(256) void k_accum(const float* __restrict__ x) {
    __shared__ float zsh[8][KK * 32];
    int w = threadIdx.x >> 5, lane = threadIdx.x & 31;
    int n = blockIdx.x * 8 + w;
    if (n >= N_NODES) return;

    #pragma unroll
    for (int j = lane; j < KK * 32; j += 32) zsh[w][j] = 0.0f;

    int start = g_off[n], end = g_off[n + 1];
    for (int e = start; e < end; ++e) {
        float4 ed = g_edata[e];                 // uniform broadcast
        int   col  = __float_as_int(ed.x);
        float fx   = ed.y, fy = ed.z;
        int   base = __float_as_int(ed.w);
        float xv = x[col * CIN_ + lane];        // coalesced random gather
        float gx = 1.0f - fx, gy = 1.0f - fy;
        zsh[w][(base    ) * 32 + lane] += gx * gy * xv;
        zsh[w][(base + 1) * 32 + lane] += fx * gy * xv;
        zsh[w][(base + 5) * 32 + lane] += gx * fy * xv;
        zsh[w][(base + 6) * 32 + lane] += fx * fy * xv;
    }

    float inv = 1.0f / fmaxf((float)(end - start), 1.0f);
    size_t zb = (size_t)n * RDIM;
    #pragma unroll
    for (int j = 0; j < KK; ++j)
        g_zp[zb + j * 32 + lane] = pack_bf16x2(zsh[w][j * 32 + lane] * inv);
    g_zp[zb + KK * 32 + lane] = pack_bf16x2(x[n * CIN_ + lane]);   // root slot
}

// ---------------- tensor-core GEMM via mma.sync m16n8k16 bf16 (2-term split) ----------------
// block: 128 rows x 64 cols, 8 warps (warp w: rows w*16.., all 64 cols)
// smem planes (uint32 words, pitch WPITCH=36): Ah[128], Al[128], Bh[64], Bl[64]
#define SW_AH 0
#define SW_AL (128 * WPITCH)                  // 4608
#define SW_BH (256 * WPITCH)                  // 9216
#define SW_BL (256 * WPITCH + 64 * WPITCH)    // 11520
#define SW_WORDS (256 * WPITCH + 128 * WPITCH) // 13824
#define SM_BYTES (SW_WORDS * 4)               // 55296

__device__ __forceinline__ void mma_bf16(float* c, const uint32_t* a, const uint32_t* b) {
    asm volatile(
        "mma.sync.aligned.m16n8k16.row.col.f32.bf16.bf16.f32 "
        "{%0,%1,%2,%3}, {%4,%5,%6,%7}, {%8,%9}, {%0,%1,%2,%3};"
        : "+f"(c[0]), "+f"(c[1]), "+f"(c[2]), "+f"(c[3])
        : "r"(a[0]), "r"(a[1]), "r"(a[2]), "r"(a[3]), "r"(b[0]), "r"(b[1]));
}

__global__ __launch_bounds__(256) void k_gemm_mma(const float* __restrict__ bias,
                                                  float* __restrict__ out) {
    extern __shared__ uint32_t smu[];
    int tid = threadIdx.x, w = tid >> 5, lane = tid & 31;
    int n0 = blockIdx.x * TILE_M;
    int qr = lane >> 2, qc = lane & 3;

    float acc[8][4];
    #pragma unroll
    for (int nt = 0; nt < 8; ++nt)
        #pragma unroll
        for (int i = 0; i < 4; ++i) acc[nt][i] = 0.0f;

    for (int ch = 0; ch < CHUNKS; ++ch) {
        int r0 = ch * KCHUNK;
        __syncthreads();
        // stage A: 128 rows x 64 packed words = 2048 uint4, unpack hi/lo planes
        #pragma unroll
        for (int it = 0; it < 8; ++it) {
            int idx = it * 256 + tid;
            int row = idx >> 4, q = idx & 15;      // q: uint4 index within row (16/row)
            int n = n0 + row;
            uint4 p = make_uint4(0u, 0u, 0u, 0u);
            if (n < N_NODES) p = *(const uint4*)&g_zp[(size_t)n * RDIM + r0 + q * 4];
            uint32_t h0 = __byte_perm(p.x, p.y, 0x7632);
            uint32_t l0 = __byte_perm(p.x, p.y, 0x5410);
            uint32_t h1 = __byte_perm(p.z, p.w, 0x7632);
            uint32_t l1 = __byte_perm(p.z, p.w, 0x5410);
            int o = row * WPITCH + q * 2;
            *(uint2*)&smu[SW_AH + o] = make_uint2(h0, h1);
            *(uint2*)&smu[SW_AL + o] = make_uint2(l0, l1);
        }
        // stage B: 64 rows x 64 packed words = 1024 uint4
        #pragma unroll
        for (int it = 0; it < 4; ++it) {
            int idx = it * 256 + tid;
            int row = idx >> 4, q = idx & 15;
            uint4 p = *(const uint4*)&g_wtp[row * RDIM + r0 + q * 4];
            uint32_t h0 = __byte_perm(p.x, p.y, 0x7632);
            uint32_t l0 = __byte_perm(p.x, p.y, 0x5410);
            uint32_t h1 = __byte_perm(p.z, p.w, 0x7632);
            uint32_t l1 = __byte_perm(p.z, p.w, 0x5410);
            int o = row * WPITCH + q * 2;
            *(uint2*)&smu[SW_BH + o] = make_uint2(h0, h1);
            *(uint2*)&smu[SW_BL + o] = make_uint2(l0, l1);
        }
        __syncthreads();

        #pragma unroll
        for (int ks = 0; ks < KCHUNK / 16; ++ks) {   // 4 k-steps of 16
            int kw = ks * 8;                          // word offset
            int ab = (w * 16 + qr) * WPITCH + kw + qc;
            uint32_t ah[4], al[4];
            ah[0] = smu[SW_AH + ab];
            ah[1] = smu[SW_AH + ab + 8 * WPITCH];
            ah[2] = smu[SW_AH + ab + 4];
            ah[3] = smu[SW_AH + ab + 8 * WPITCH + 4];
            al[0] = smu[SW_AL + ab];
            al[1] = smu[SW_AL + ab + 8 * WPITCH];
            al[2] = smu[SW_AL + ab + 4];
            al[3] = smu[SW_AL + ab + 8 * WPITCH + 4];
            #pragma unroll
            for (int nt = 0; nt < 8; ++nt) {
                int bb = (nt * 8 + qr) * WPITCH + kw + qc;
                uint32_t bh[2], bl[2];
                bh[0] = smu[SW_BH + bb];
                bh[1] = smu[SW_BH + bb + 4];
                bl[0] = smu[SW_BL + bb];
                bl[1] = smu[SW_BL + bb + 4];
                mma_bf16(acc[nt], ah, bh);
                mma_bf16(acc[nt], ah, bl);
                mma_bf16(acc[nt], al, bh);
            }
        }
    }

    // epilogue: c0,c1 -> (row, 2qc..2qc+1); c2,c3 -> row+8
    int rowa = n0 + w * 16 + qr;
    int rowb = rowa + 8;
    #pragma unroll
    for (int nt = 0; nt < 8; ++nt) {
        int col = nt * 8 + 2 * qc;
        float b0 = bias[col], b1 = bias[col + 1];
        if (rowa < N_NODES)
            *(float2*)&out[rowa * COUT_ + col] = make_float2(acc[nt][0] + b0, acc[nt][1] + b1);
        if (rowb < N_NODES)
            *(float2*)&out[rowb * COUT_ + col] = make_float2(acc[nt][2] + b0, acc[nt][3] + b1);
    }
}

// ---------------- launch ----------------
extern "C" void kernel_launch(void* const* d_in, const int* in_sizes, int n_in,
                              void* d_out, int out_size) {
    const float* x      = (const float*)d_in[0];
    const int*   ei     = (const int*)d_in[1];      // JAX x64-disabled: int32
    const float* pseudo = (const float*)d_in[2];
    const float* weight = (const float*)d_in[3];
    const float* root   = (const float*)d_in[4];
    const float* bias   = (const float*)d_in[5];
    float*       out    = (float*)d_out;

    static bool attr_done = false;
    if (!attr_done) {
        cudaFuncSetAttribute(k_gemm_mma, cudaFuncAttributeMaxDynamicSharedMemorySize, SM_BYTES);
        attr_done = true;
    }

    k_zero_deg<<<(N_NODES + 255) / 256, 256>>>();
    k_hist    <<<(E_EDGES + 255) / 256, 256>>>(ei);
    k_bsum    <<<NB, 256>>>();
    k_bscan   <<<1, 256>>>();
    k_offsets <<<NB, 256>>>();
    k_scatter <<<(E_EDGES + 255) / 256, 256>>>(ei, pseudo);
    k_prep_wt <<<(COUT_ * RDIM + 255) / 256, 256>>>(weight, root);
    k_accum   <<<(N_NODES + 7) / 8, 256>>>(x);
    k_gemm_mma<<<N_TILES, 256, SM_BYTES>>>(bias, out);
}

// round 8
// speedup vs baseline: 2.1068x; 1.3624x over previous
#include <cuda_runtime.h>
#include <cuda_bf16.h>
#include <cstdint>

#define N_NODES 50000
#define N_PAD 50048              // padded row count for unpredicated staging
#define E_EDGES 800000
#define CIN_ 32
#define COUT_ 64
#define KK 25
#define RDIM 832                 // 26 * 32  (25 spline kernels + 1 root slot)
#define TILE_M 128
#define N_TILES ((N_NODES + TILE_M - 1) / TILE_M)   // 391
#define KCHUNK 64                // K elements per smem chunk
#define CHUNKS (RDIM / KCHUNK)   // 13
#define WP 72                    // packed smem row pitch (words); 8*qr+2*qc conflict-free
#define NB 196                   // scan blocks: ceil(50000/256)

// ---- scratch (static device globals; no allocation) ----
__device__ int      g_deg[N_NODES];
__device__ int      g_off[N_NODES + 1];
__device__ int      g_cursor[N_NODES];
__device__ int      g_bsum[NB];
__device__ int      g_boff[NB];
__device__ float4   g_edata[E_EDGES];              // {col, fx, fy, base} per CSR slot
__device__ uint32_t g_zp[(size_t)N_PAD * RDIM];    // packed (bf16 hi<<16 | bf16 lo)
__device__ uint32_t g_wtp[COUT_ * RDIM];           // packed Wfull^T [64][832]

__device__ __forceinline__ uint32_t pack_bf16x2(float v) {
    __nv_bfloat16 h = __float2bfloat16(v);
    float hf = __bfloat162float(h);
    __nv_bfloat16 l = __float2bfloat16(v - hf);
    return ((uint32_t)__bfloat16_as_ushort(h) << 16) | (uint32_t)__bfloat16_as_ushort(l);
}

// ---------------- CSR build ----------------
__global__ void k_zero_deg() {
    int i = blockIdx.x * blockDim.x + threadIdx.x;
    if (i < N_NODES) g_deg[i] = 0;
}

__global__ void k_hist(const int* __restrict__ ei) {
    int e = blockIdx.x * blockDim.x + threadIdx.x;
    if (e < E_EDGES) {
        int row = ei[e];
        row = min(max(row, 0), N_NODES - 1);
        atomicAdd(&g_deg[row], 1);
    }
}

__global__ __launch_bounds__(256) void k_bsum() {
    __shared__ int ws[8];
    int tid = threadIdx.x, lane = tid & 31, w = tid >> 5;
    int i = blockIdx.x * 256 + tid;
    int v = (i < N_NODES) ? g_deg[i] : 0;
    #pragma unroll
    for (int d = 16; d > 0; d >>= 1) v += __shfl_down_sync(0xffffffffu, v, d);
    if (lane == 0) ws[w] = v;
    __syncthreads();
    if (tid == 0) {
        int s = 0;
        #pragma unroll
        for (int j = 0; j < 8; ++j) s += ws[j];
        g_bsum[blockIdx.x] = s;
    }
}

__global__ __launch_bounds__(256) void k_bscan() {
    __shared__ int ws[8];
    int tid = threadIdx.x, lane = tid & 31, w = tid >> 5;
    int v = (tid < NB) ? g_bsum[tid] : 0;
    int s = v;
    #pragma unroll
    for (int d = 1; d < 32; d <<= 1) {
        int t = __shfl_up_sync(0xffffffffu, s, d);
        if (lane >= d) s += t;
    }
    if (lane == 31) ws[w] = s;
    __syncthreads();
    if (w == 0 && lane < 8) {
        int x = ws[lane];
        #pragma unroll
        for (int d = 1; d < 8; d <<= 1) {
            int t = __shfl_up_sync(0xffu, x, d);
            if (lane >= d) x += t;
        }
        ws[lane] = x;
    }
    __syncthreads();
    int woff = w ? ws[w - 1] : 0;
    if (tid < NB) g_boff[tid] = woff + s - v;
}

__global__ __launch_bounds__(256) void k_offsets() {
    __shared__ int ws[8];
    int tid = threadIdx.x, lane = tid & 31, w = tid >> 5;
    int i = blockIdx.x * 256 + tid;
    int v = (i < N_NODES) ? g_deg[i] : 0;
    int s = v;
    #pragma unroll
    for (int d = 1; d < 32; d <<= 1) {
        int t = __shfl_up_sync(0xffffffffu, s, d);
        if (lane >= d) s += t;
    }
    if (lane == 31) ws[w] = s;
    __syncthreads();
    if (w == 0 && lane < 8) {
        int x = ws[lane];
        #pragma unroll
        for (int d = 1; d < 8; d <<= 1) {
            int t = __shfl_up_sync(0xffu, x, d);
            if (lane >= d) x += t;
        }
        ws[lane] = x;
    }
    __syncthreads();
    int woff = w ? ws[w - 1] : 0;
    int excl = g_boff[blockIdx.x] + woff + s - v;
    if (i < N_NODES) {
        g_off[i] = excl;
        g_cursor[i] = excl;
        if (i == N_NODES - 1) g_off[N_NODES] = excl + v;
    }
}

__global__ void k_scatter(const int* __restrict__ ei,
                          const float* __restrict__ pseudo) {
    int e = blockIdx.x * blockDim.x + threadIdx.x;
    if (e < E_EDGES) {
        int row = ei[e];
        int col = ei[E_EDGES + e];
        row = min(max(row, 0), N_NODES - 1);
        col = min(max(col, 0), N_NODES - 1);
        float vx = pseudo[2 * e]     * 4.0f;   // (KS - DEGREE) = 4
        float vy = pseudo[2 * e + 1] * 4.0f;
        float flx = floorf(vx), fly = floorf(vy);
        float fx = vx - flx, fy = vy - fly;
        int lox = min(max((int)flx, 0), 3);
        int loy = min(max((int)fly, 0), 3);
        int base = lox + 5 * loy;
        int pos = atomicAdd(&g_cursor[row], 1);
        g_edata[pos] = make_float4(__int_as_float(col), fx, fy, __int_as_float(base));
    }
}

__global__ void k_prep_wt(const float* __restrict__ weight, const float* __restrict__ root) {
    int i = blockIdx.x * blockDim.x + threadIdx.x;   // i = o*832 + r
    if (i < COUT_ * RDIM) {
        int o = i / RDIM, r = i - o * RDIM;
        float w = (r < 800) ? weight[r * COUT_ + o] : root[(r - 800) * COUT_ + o];
        g_wtp[i] = pack_bf16x2(w);
    }
}

// ---------------- per-node z accumulation (warp per node, no atomics) ----------------
__global__ __launch_bounds__(256) void k_accum(const float* __restrict__ x) {
    __shared__ float zsh[8][KK * 32];
    int w = threadIdx.x >> 5, lane = threadIdx.x & 31;
    int n = blockIdx.x * 8 + w;
    if (n >= N_NODES) return;

    #pragma unroll
    for (int j = lane; j < KK * 32; j += 32) zsh[w][j] = 0.0f;

    int start = g_off[n], end = g_off[n + 1];
    if (end > start) {
        float4 ed = g_edata[start];
        for (int e = start; e < end; ++e) {
            float4 edn;
            if (e + 1 < end) edn = g_edata[e + 1];   // prefetch next (MLP 2)
            int   col  = __float_as_int(ed.x);
            float fx   = ed.y, fy = ed.z;
            int   base = __float_as_int(ed.w);
            float xv = x[col * CIN_ + lane];
            float gx = 1.0f - fx, gy = 1.0f - fy;
            zsh[w][(base    ) * 32 + lane] += gx * gy * xv;
            zsh[w][(base + 1) * 32 + lane] += fx * gy * xv;
            zsh[w][(base + 5) * 32 + lane] += gx * fy * xv;
            zsh[w][(base + 6) * 32 + lane] += fx * fy * xv;
            ed = edn;
        }
    }

    float inv = 1.0f / fmaxf((float)(end - start), 1.0f);
    size_t zb = (size_t)n * RDIM;
    #pragma unroll
    for (int j = 0; j < KK; ++j)
        g_zp[zb + j * 32 + lane] = pack_bf16x2(zsh[w][j * 32 + lane] * inv);
    g_zp[zb + KK * 32 + lane] = pack_bf16x2(x[n * CIN_ + lane]);   // root slot
}

// ---------------- GEMM: packed smem + cp.async double buffer + m16n8k16 bf16 x3 ----------------
// stage: Ap[128][WP] + Bp[64][WP] packed words; 2 stages
#define STAGE_WORDS ((128 + 64) * WP)            // 13824
#define SM_BYTES (2 * STAGE_WORDS * 4)           // 110592

#define CP16(dst, src) asm volatile("cp.async.cg.shared.global [%0], [%1], 16;" :: "r"(dst), "l"(src))
#define CP_COMMIT()    asm volatile("cp.async.commit_group;" ::: "memory")
#define CP_WAIT(n)     asm volatile("cp.async.wait_group %0;" :: "n"(n) : "memory")

__device__ __forceinline__ void mma_bf16(float* c, const uint32_t* a, const uint32_t* b) {
    asm volatile(
        "mma.sync.aligned.m16n8k16.row.col.f32.bf16.bf16.f32 "
        "{%0,%1,%2,%3}, {%4,%5,%6,%7}, {%8,%9}, {%0,%1,%2,%3};"
        : "+f"(c[0]), "+f"(c[1]), "+f"(c[2]), "+f"(c[3])
        : "r"(a[0]), "r"(a[1]), "r"(a[2]), "r"(a[3]), "r"(b[0]), "r"(b[1]));
}

__global__ __launch_bounds__(256) void k_gemm_mma(const float* __restrict__ bias,
                                                  float* __restrict__ out) {
    extern __shared__ uint32_t smu[];
    int tid = threadIdx.x, w = tid >> 5, lane = tid & 31;
    int n0 = blockIdx.x * TILE_M;
    int qr = lane >> 2, qc = lane & 3;

    // staging indices (fixed per thread): A: 8 x 16B, B: 4 x 16B
    uint32_t sm_base = (uint32_t)__cvta_generic_to_shared(smu);

    float acc[8][4];
    #pragma unroll
    for (int nt = 0; nt < 8; ++nt)
        #pragma unroll
        for (int i = 0; i < 4; ++i) acc[nt][i] = 0.0f;

    // ---- stage chunk `ch` into stage buffer `s` ----
    auto stage = [&](int ch, int s) {
        int r0 = ch * KCHUNK;
        uint32_t ab = sm_base + (uint32_t)(s * STAGE_WORDS) * 4u;
        uint32_t bb = ab + 128u * WP * 4u;
        #pragma unroll
        for (int it = 0; it < 8; ++it) {
            int idx = it * 256 + tid;
            int row = idx >> 4, q = idx & 15;
            const uint32_t* src = &g_zp[(size_t)(n0 + row) * RDIM + r0 + q * 4];
            CP16(ab + (uint32_t)(row * WP + q * 4) * 4u, src);
        }
        #pragma unroll
        for (int it = 0; it < 4; ++it) {
            int idx = it * 256 + tid;
            int row = idx >> 4, q = idx & 15;
            const uint32_t* src = &g_wtp[row * RDIM + r0 + q * 4];
            CP16(bb + (uint32_t)(row * WP + q * 4) * 4u, src);
        }
        CP_COMMIT();
    };

    stage(0, 0);

    for (int ch = 0; ch < CHUNKS; ++ch) {
        if (ch + 1 < CHUNKS) {
            stage(ch + 1, (ch + 1) & 1);
            CP_WAIT(1);
        } else {
            CP_WAIT(0);
        }
        __syncthreads();

        const uint32_t* Ap = smu + (ch & 1) * STAGE_WORDS;
        const uint32_t* Bp = Ap + 128 * WP;

        #pragma unroll
        for (int ks = 0; ks < KCHUNK / 16; ++ks) {
            int kb = ks * 16;                                  // k-element base
            int ar = (w * 16 + qr) * WP + kb + 2 * qc;
            uint2 pa0 = *(const uint2*)&Ap[ar];                // rows qr   , k 2qc..+1
            uint2 pa1 = *(const uint2*)&Ap[ar + 8 * WP];       // rows qr+8
            uint2 pa2 = *(const uint2*)&Ap[ar + 8];            // k +8
            uint2 pa3 = *(const uint2*)&Ap[ar + 8 * WP + 8];
            uint32_t ah[4], al[4];
            ah[0] = __byte_perm(pa0.x, pa0.y, 0x7632); al[0] = __byte_perm(pa0.x, pa0.y, 0x5410);
            ah[1] = __byte_perm(pa1.x, pa1.y, 0x7632); al[1] = __byte_perm(pa1.x, pa1.y, 0x5410);
            ah[2] = __byte_perm(pa2.x, pa2.y, 0x7632); al[2] = __byte_perm(pa2.x, pa2.y, 0x5410);
            ah[3] = __byte_perm(pa3.x, pa3.y, 0x7632); al[3] = __byte_perm(pa3.x, pa3.y, 0x5410);
            #pragma unroll
            for (int nt = 0; nt < 8; ++nt) {
                int br = (nt * 8 + qr) * WP + kb + 2 * qc;
                uint2 pb0 = *(const uint2*)&Bp[br];
                uint2 pb1 = *(const uint2*)&Bp[br + 8];
                uint32_t bh[2], bl[2];
                bh[0] = __byte_perm(pb0.x, pb0.y, 0x7632); bl[0] = __byte_perm(pb0.x, pb0.y, 0x5410);
                bh[1] = __byte_perm(pb1.x, pb1.y, 0x7632); bl[1] = __byte_perm(pb1.x, pb1.y, 0x5410);
                mma_bf16(acc[nt], ah, bh);
                mma_bf16(acc[nt], ah, bl);
                mma_bf16(acc[nt], al, bh);
            }
        }
        __syncthreads();
    }

    // epilogue: c0,c1 -> (row, 2qc..2qc+1); c2,c3 -> row+8
    int rowa = n0 + w * 16 + qr;
    int rowb = rowa + 8;
    #pragma unroll
    for (int nt = 0; nt < 8; ++nt) {
        int col = nt * 8 + 2 * qc;
        float b0 = bias[col], b1 = bias[col + 1];
        if (rowa < N_NODES)
            *(float2*)&out[rowa * COUT_ + col] = make_float2(acc[nt][0] + b0, acc[nt][1] + b1);
        if (rowb < N_NODES)
            *(float2*)&out[rowb * COUT_ + col] = make_float2(acc[nt][2] + b0, acc[nt][3] + b1);
    }
}

// ---------------- launch ----------------
extern "C" void kernel_launch(void* const* d_in, const int* in_sizes, int n_in,
                              void* d_out, int out_size) {
    const float* x      = (const float*)d_in[0];
    const int*   ei     = (const int*)d_in[1];      // JAX x64-disabled: int32
    const float* pseudo = (const float*)d_in[2];
    const float* weight = (const float*)d_in[3];
    const float* root   = (const float*)d_in[4];
    const float* bias   = (const float*)d_in[5];
    float*       out    = (float*)d_out;

    static bool attr_done = false;
    if (!attr_done) {
        cudaFuncSetAttribute(k_gemm_mma, cudaFuncAttributeMaxDynamicSharedMemorySize, SM_BYTES);
        attr_done = true;
    }

    k_zero_deg<<<(N_NODES + 255) / 256, 256>>>();
    k_hist    <<<(E_EDGES + 255) / 256, 256>>>(ei);
    k_bsum    <<<NB, 256>>>();
    k_bscan   <<<1, 256>>>();
    k_offsets <<<NB, 256>>>();
    k_scatter <<<(E_EDGES + 255) / 256, 256>>>(ei, pseudo);
    k_prep_wt <<<(COUT_ * RDIM + 255) / 256, 256>>>(weight, root);
    k_accum   <<<(N_NODES + 7) / 8, 256>>>(x);
    k_gemm_mma<<<N_TILES, 256, SM_BYTES>>>(bias, out);
}

// round 9
// speedup vs baseline: 2.4608x; 1.1680x over previous
#include <cuda_runtime.h>
#include <cuda_fp16.h>
#include <cstdint>

#define N_NODES 50000
#define N_PAD 50048              // padded row count for unpredicated staging
#define E_EDGES 800000
#define CIN_ 32
#define COUT_ 64
#define KK 25
#define RDIM 832                 // 26 * 32  (25 spline kernels + 1 root slot)
#define RW 416                   // words per z row (fp16 pairs)
#define TILE_M 128
#define N_TILES ((N_NODES + TILE_M - 1) / TILE_M)   // 391
#define KCHUNK 64                // K elements per chunk
#define KW 32                    // words per chunk row
#define CHUNKS (RDIM / KCHUNK)   // 13
#define P 36                     // smem row pitch (words); qr*36+qc ≡ qr*4+qc conflict-free
#define NB 196                   // scan blocks: ceil(50000/256)
#define NWT (COUT_ * RW)         // 26624 weight words

// ---- scratch (static device globals; no allocation) ----
__device__ int      g_deg[N_NODES];
__device__ int      g_off[N_NODES + 1];
__device__ int      g_cursorp[N_NODES * 8];        // stride-8: distinct 32B sectors
__device__ int      g_bsum[NB];
__device__ int      g_boff[NB];
__device__ float4   g_edata[E_EDGES];              // {col, fx, fy, base} per CSR slot
__device__ uint32_t g_zh[(size_t)N_PAD * RW];      // z as fp16 pairs, 83 MB
__device__ uint32_t g_wth[NWT];                    // Wfull^T hi fp16 pairs [64][416]
__device__ uint32_t g_wtl[NWT];                    // Wfull^T lo (residual) fp16 pairs

__device__ __forceinline__ uint32_t pack_h2(float a, float b) {
    __half2 h = __floats2half2_rn(a, b);
    return *(uint32_t*)&h;
}

// ---------------- init: zero deg + prep Wfull^T hi/lo ----------------
__global__ void k_init(const float* __restrict__ weight, const float* __restrict__ root) {
    int i = blockIdx.x * blockDim.x + threadIdx.x;
    if (i < N_NODES) g_deg[i] = 0;
    if (i < NWT) {
        int o = i / RW, j = i - o * RW;
        int r0 = 2 * j, r1 = 2 * j + 1;
        float w0 = (r0 < 800) ? weight[r0 * COUT_ + o] : root[(r0 - 800) * COUT_ + o];
        float w1 = (r1 < 800) ? weight[r1 * COUT_ + o] : root[(r1 - 800) * COUT_ + o];
        float h0 = __half2float(__float2half_rn(w0));
        float h1 = __half2float(__float2half_rn(w1));
        g_wth[i] = pack_h2(h0, h1);
        g_wtl[i] = pack_h2(w0 - h0, w1 - h1);
    }
}

__global__ void k_hist(const int* __restrict__ ei) {
    int e = blockIdx.x * blockDim.x + threadIdx.x;
    if (e < E_EDGES) {
        int row = ei[e];
        row = min(max(row, 0), N_NODES - 1);
        atomicAdd(&g_deg[row], 1);
    }
}

__global__ __launch_bounds__(256) void k_bsum() {
    __shared__ int ws[8];
    int tid = threadIdx.x, lane = tid & 31, w = tid >> 5;
    int i = blockIdx.x * 256 + tid;
    int v = (i < N_NODES) ? g_deg[i] : 0;
    #pragma unroll
    for (int d = 16; d > 0; d >>= 1) v += __shfl_down_sync(0xffffffffu, v, d);
    if (lane == 0) ws[w] = v;
    __syncthreads();
    if (tid == 0) {
        int s = 0;
        #pragma unroll
        for (int j = 0; j < 8; ++j) s += ws[j];
        g_bsum[blockIdx.x] = s;
    }
}

__global__ __launch_bounds__(256) void k_bscan() {
    __shared__ int ws[8];
    int tid = threadIdx.x, lane = tid & 31, w = tid >> 5;
    int v = (tid < NB) ? g_bsum[tid] : 0;
    int s = v;
    #pragma unroll
    for (int d = 1; d < 32; d <<= 1) {
        int t = __shfl_up_sync(0xffffffffu, s, d);
        if (lane >= d) s += t;
    }
    if (lane == 31) ws[w] = s;
    __syncthreads();
    if (w == 0 && lane < 8) {
        int x = ws[lane];
        #pragma unroll
        for (int d = 1; d < 8; d <<= 1) {
            int t = __shfl_up_sync(0xffu, x, d);
            if (lane >= d) x += t;
        }
        ws[lane] = x;
    }
    __syncthreads();
    int woff = w ? ws[w - 1] : 0;
    if (tid < NB) g_boff[tid] = woff + s - v;
}

__global__ __launch_bounds__(256) void k_offsets() {
    __shared__ int ws[8];
    int tid = threadIdx.x, lane = tid & 31, w = tid >> 5;
    int i = blockIdx.x * 256 + tid;
    int v = (i < N_NODES) ? g_deg[i] : 0;
    int s = v;
    #pragma unroll
    for (int d = 1; d < 32; d <<= 1) {
        int t = __shfl_up_sync(0xffffffffu, s, d);
        if (lane >= d) s += t;
    }
    if (lane == 31) ws[w] = s;
    __syncthreads();
    if (w == 0 && lane < 8) {
        int x = ws[lane];
        #pragma unroll
        for (int d = 1; d < 8; d <<= 1) {
            int t = __shfl_up_sync(0xffu, x, d);
            if (lane >= d) x += t;
        }
        ws[lane] = x;
    }
    __syncthreads();
    int woff = w ? ws[w - 1] : 0;
    int excl = g_boff[blockIdx.x] + woff + s - v;
    if (i < N_NODES) {
        g_off[i] = excl;
        g_cursorp[i * 8] = excl;
        if (i == N_NODES - 1) g_off[N_NODES] = excl + v;
    }
}

__global__ void k_scatter(const int* __restrict__ ei,
                          const float* __restrict__ pseudo) {
    int e = blockIdx.x * blockDim.x + threadIdx.x;
    if (e < E_EDGES) {
        int row = ei[e];
        int col = ei[E_EDGES + e];
        row = min(max(row, 0), N_NODES - 1);
        col = min(max(col, 0), N_NODES - 1);
        float vx = pseudo[2 * e]     * 4.0f;   // (KS - DEGREE) = 4
        float vy = pseudo[2 * e + 1] * 4.0f;
        float flx = floorf(vx), fly = floorf(vy);
        float fx = vx - flx, fy = vy - fly;
        int lox = min(max((int)flx, 0), 3);
        int loy = min(max((int)fly, 0), 3);
        int base = lox + 5 * loy;
        int pos = atomicAdd(&g_cursorp[row * 8], 1);
        g_edata[pos] = make_float4(__int_as_float(col), fx, fy, __int_as_float(base));
    }
}

// ---------------- per-node z accumulation (warp per node, no atomics) ----------------
__global__ __launch_bounds__(256) void k_accum(const float* __restrict__ x) {
    __shared__ float zsh[8][KK * 32];
    int w = threadIdx.x >> 5, lane = threadIdx.x & 31;
    int n = blockIdx.x * 8 + w;
    if (n >= N_NODES) return;

    #pragma unroll
    for (int j = lane; j < KK * 32; j += 32) zsh[w][j] = 0.0f;

    int start = g_off[n], end = g_off[n + 1];
    if (end > start) {
        float4 ed = g_edata[start];
        for (int e = start; e < end; ++e) {
            float4 edn;
            if (e + 1 < end) edn = g_edata[e + 1];   // prefetch next (MLP 2)
            int   col  = __float_as_int(ed.x);
            float fx   = ed.y, fy = ed.z;
            int   base = __float_as_int(ed.w);
            float xv = x[col * CIN_ + lane];
            float gx = 1.0f - fx, gy = 1.0f - fy;
            zsh[w][(base    ) * 32 + lane] += gx * gy * xv;
            zsh[w][(base + 1) * 32 + lane] += fx * gy * xv;
            zsh[w][(base + 5) * 32 + lane] += gx * fy * xv;
            zsh[w][(base + 6) * 32 + lane] += fx * fy * xv;
            ed = edn;
        }
    }

    float inv = 1.0f / fmaxf((float)(end - start), 1.0f);
    size_t zb = (size_t)n * RW;
    #pragma unroll 4
    for (int widx = lane; widx < RW; widx += 32) {
        int k = widx >> 4, l = widx & 15;
        float v0, v1;
        if (k < KK) {
            v0 = zsh[w][k * 32 + 2 * l]     * inv;
            v1 = zsh[w][k * 32 + 2 * l + 1] * inv;
        } else {                               // root slot: raw x
            v0 = x[n * CIN_ + 2 * l];
            v1 = x[n * CIN_ + 2 * l + 1];
        }
        g_zh[zb + widx] = pack_h2(v0, v1);
    }
}

// ---------------- GEMM: fp16 A x (hi+lo fp16 B), cp.async double buffer ----------------
// stage layout (words): A[128][P] | Bh[64][P] | Bl[64][P]
#define ST_A  0
#define ST_BH (128 * P)
#define ST_BL (128 * P + 64 * P)
#define STAGE_WORDS ((128 + 64 + 64) * P)        // 9216
#define SM_BYTES (2 * STAGE_WORDS * 4)           // 73728

#define CP16(dst, src) asm volatile("cp.async.cg.shared.global [%0], [%1], 16;" :: "r"(dst), "l"(src))
#define CP_COMMIT()    asm volatile("cp.async.commit_group;" ::: "memory")
#define CP_WAIT(n)     asm volatile("cp.async.wait_group %0;" :: "n"(n) : "memory")

__device__ __forceinline__ void mma_f16(float* c, const uint32_t* a, const uint32_t* b) {
    asm volatile(
        "mma.sync.aligned.m16n8k16.row.col.f32.f16.f16.f32 "
        "{%0,%1,%2,%3}, {%4,%5,%6,%7}, {%8,%9}, {%0,%1,%2,%3};"
        : "+f"(c[0]), "+f"(c[1]), "+f"(c[2]), "+f"(c[3])
        : "r"(a[0]), "r"(a[1]), "r"(a[2]), "r"(a[3]), "r"(b[0]), "r"(b[1]));
}

__global__ __launch_bounds__(256) void k_gemm_mma(const float* __restrict__ bias,
                                                  float* __restrict__ out) {
    extern __shared__ uint32_t smu[];
    int tid = threadIdx.x, w = tid >> 5, lane = tid & 31;
    int n0 = blockIdx.x * TILE_M;
    int qr = lane >> 2, qc = lane & 3;

    uint32_t sm_base = (uint32_t)__cvta_generic_to_shared(smu);

    float acc[8][4];
    #pragma unroll
    for (int nt = 0; nt < 8; ++nt)
        #pragma unroll
        for (int i = 0; i < 4; ++i) acc[nt][i] = 0.0f;

    auto stage = [&](int ch, int s) {
        int w0 = ch * KW;
        uint32_t base = sm_base + (uint32_t)(s * STAGE_WORDS) * 4u;
        #pragma unroll
        for (int it = 0; it < 4; ++it) {         // A: 128 rows x 8 uint4
            int idx = it * 256 + tid;
            int row = idx >> 3, q = idx & 7;
            const uint32_t* src = &g_zh[(size_t)(n0 + row) * RW + w0 + q * 4];
            CP16(base + (uint32_t)(ST_A + row * P + q * 4) * 4u, src);
        }
        #pragma unroll
        for (int it = 0; it < 2; ++it) {         // Bh: 64 rows x 8 uint4
            int idx = it * 256 + tid;
            int row = idx >> 3, q = idx & 7;
            CP16(base + (uint32_t)(ST_BH + row * P + q * 4) * 4u, &g_wth[row * RW + w0 + q * 4]);
        }
        #pragma unroll
        for (int it = 0; it < 2; ++it) {         // Bl
            int idx = it * 256 + tid;
            int row = idx >> 3, q = idx & 7;
            CP16(base + (uint32_t)(ST_BL + row * P + q * 4) * 4u, &g_wtl[row * RW + w0 + q * 4]);
        }
        CP_COMMIT();
    };

    stage(0, 0);

    for (int ch = 0; ch < CHUNKS; ++ch) {
        if (ch + 1 < CHUNKS) {
            stage(ch + 1, (ch + 1) & 1);
            CP_WAIT(1);
        } else {
            CP_WAIT(0);
        }
        __syncthreads();

        const uint32_t* Ap  = smu + (ch & 1) * STAGE_WORDS;
        const uint32_t* Bh  = Ap + ST_BH;
        const uint32_t* Bl  = Ap + ST_BL;

        #pragma unroll
        for (int ks = 0; ks < KW / 8; ++ks) {          // 4 k-steps of 16 elems (8 words)
            int kb = ks * 8;
            int ar = (w * 16 + qr) * P + kb + qc;
            uint32_t a[4];
            a[0] = Ap[ar];
            a[1] = Ap[ar + 8 * P];
            a[2] = Ap[ar + 4];
            a[3] = Ap[ar + 8 * P + 4];
            #pragma unroll
            for (int nt = 0; nt < 8; ++nt) {
                int br = (nt * 8 + qr) * P + kb + qc;
                uint32_t bh[2], bl[2];
                bh[0] = Bh[br]; bh[1] = Bh[br + 4];
                bl[0] = Bl[br]; bl[1] = Bl[br + 4];
                mma_f16(acc[nt], a, bh);
                mma_f16(acc[nt], a, bl);
            }
        }
        __syncthreads();
    }

    // epilogue: c0,c1 -> (row, 2qc..2qc+1); c2,c3 -> row+8
    int rowa = n0 + w * 16 + qr;
    int rowb = rowa + 8;
    #pragma unroll
    for (int nt = 0; nt < 8; ++nt) {
        int col = nt * 8 + 2 * qc;
        float b0 = bias[col], b1 = bias[col + 1];
        if (rowa < N_NODES)
            *(float2*)&out[rowa * COUT_ + col] = make_float2(acc[nt][0] + b0, acc[nt][1] + b1);
        if (rowb < N_NODES)
            *(float2*)&out[rowb * COUT_ + col] = make_float2(acc[nt][2] + b0, acc[nt][3] + b1);
    }
}

// ---------------- launch ----------------
extern "C" void kernel_launch(void* const* d_in, const int* in_sizes, int n_in,
                              void* d_out, int out_size) {
    const float* x      = (const float*)d_in[0];
    const int*   ei     = (const int*)d_in[1];      // JAX x64-disabled: int32
    const float* pseudo = (const float*)d_in[2];
    const float* weight = (const float*)d_in[3];
    const float* root   = (const float*)d_in[4];
    const float* bias   = (const float*)d_in[5];
    float*       out    = (float*)d_out;

    static bool attr_done = false;
    if (!attr_done) {
        cudaFuncSetAttribute(k_gemm_mma, cudaFuncAttributeMaxDynamicSharedMemorySize, SM_BYTES);
        attr_done = true;
    }

    k_init    <<<(N_NODES + 255) / 256, 256>>>(weight, root);
    k_hist    <<<(E_EDGES + 255) / 256, 256>>>(ei);
    k_bsum    <<<NB, 256>>>();
    k_bscan   <<<1, 256>>>();
    k_offsets <<<NB, 256>>>();
    k_scatter <<<(E_EDGES + 255) / 256, 256>>>(ei, pseudo);
    k_accum   <<<(N_NODES + 7) / 8, 256>>>(x);
    k_gemm_mma<<<N_TILES, 256, SM_BYTES>>>(bias, out);
}